// round 9
// baseline (speedup 1.0000x reference)
#include <cuda_runtime.h>
#include <cuda_fp16.h>
#include <cuda_bf16.h>
#include <cstdint>

#define NN 50000
#define NE 800000
#define F  128

// ---------------- scratch (static device globals) ---------------------------
__device__ __align__(16) int    g_deg[NN];
__device__ __align__(16) int    g_cursor[NN];
__device__ __align__(16) int    g_rowptr[NN + 1];   // block-local exclusive scan
__device__ __align__(16) int    g_csrc[NE];
__device__ __align__(16) __half g_ABh[(size_t)NN * 256];
__device__ __align__(16) int    g_bsum[64];
__device__ __align__(16) int    g_boff[64];
__device__ int g_is64;

// fp16 gather tables for aggregation
__device__ __align__(16) __half g_x16[NN * F];
__device__ __align__(16) __half g_h1h16[NN * F];
// bf16 hi/lo split operand tables (GEMM A operands)
__device__ __align__(16) __nv_bfloat16 g_xhi[NN * F],  g_xlo[NN * F];
__device__ __align__(16) __nv_bfloat16 g_mhi[NN * F],  g_mlo[NN * F];
__device__ __align__(16) __nv_bfloat16 g_h1hi[NN * F], g_h1lo[NN * F];
__device__ __align__(16) __nv_bfloat16 g_h2hi[NN * F], g_h2lo[NN * F];
// weights transposed+split: wt[n][k]; wt1 @0 (K=256), wt2 @32768 (K=256), wtc @65536 (256 rows x 128)
__device__ __align__(16) __nv_bfloat16 g_wt_hi[98304], g_wt_lo[98304];

// ---------------- helpers -----------------------------------------------------
__device__ __forceinline__ uint32_t sm32(const void* p) {
    uint32_t a;
    asm("{ .reg .u64 t; cvta.to.shared.u64 t, %1; cvt.u32.u64 %0, t; }"
        : "=r"(a) : "l"(p));
    return a;
}

__device__ __forceinline__ void ldm_x4(uint32_t (&r)[4], uint32_t addr) {
    asm volatile("ldmatrix.sync.aligned.m8n8.x4.shared.b16 {%0,%1,%2,%3}, [%4];"
        : "=r"(r[0]), "=r"(r[1]), "=r"(r[2]), "=r"(r[3]) : "r"(addr));
}
__device__ __forceinline__ void ldm_x2(uint32_t (&r)[2], uint32_t addr) {
    asm volatile("ldmatrix.sync.aligned.m8n8.x2.shared.b16 {%0,%1}, [%2];"
        : "=r"(r[0]), "=r"(r[1]) : "r"(addr));
}
__device__ __forceinline__ void mma16816(float (&d)[4], const uint32_t (&a)[4],
                                         const uint32_t (&b)[2]) {
    asm volatile("mma.sync.aligned.m16n8k16.row.col.f32.bf16.bf16.f32 "
        "{%0,%1,%2,%3}, {%4,%5,%6,%7}, {%8,%9}, {%0,%1,%2,%3};"
        : "+f"(d[0]), "+f"(d[1]), "+f"(d[2]), "+f"(d[3])
        : "r"(a[0]), "r"(a[1]), "r"(a[2]), "r"(a[3]), "r"(b[0]), "r"(b[1]));
}

__device__ __forceinline__ unsigned short bfu(__nv_bfloat16 h) {
    return __bfloat16_as_ushort(h);
}
__device__ __forceinline__ void split4(float4 v, uint2& hi, uint2& lo) {
    __nv_bfloat16 h0 = __float2bfloat16(v.x), h1 = __float2bfloat16(v.y);
    __nv_bfloat16 h2 = __float2bfloat16(v.z), h3 = __float2bfloat16(v.w);
    float r0 = v.x - __bfloat162float(h0), r1 = v.y - __bfloat162float(h1);
    float r2 = v.z - __bfloat162float(h2), r3 = v.w - __bfloat162float(h3);
    __nv_bfloat16 l0 = __float2bfloat16(r0), l1 = __float2bfloat16(r1);
    __nv_bfloat16 l2 = __float2bfloat16(r2), l3 = __float2bfloat16(r3);
    hi.x = (unsigned)bfu(h0) | ((unsigned)bfu(h1) << 16);
    hi.y = (unsigned)bfu(h2) | ((unsigned)bfu(h3) << 16);
    lo.x = (unsigned)bfu(l0) | ((unsigned)bfu(l1) << 16);
    lo.y = (unsigned)bfu(l2) | ((unsigned)bfu(l3) << 16);
}
__device__ __forceinline__ void split2(float x, float y, unsigned& hi, unsigned& lo) {
    __nv_bfloat16 h0 = __float2bfloat16(x), h1 = __float2bfloat16(y);
    float r0 = x - __bfloat162float(h0), r1 = y - __bfloat162float(h1);
    hi = (unsigned)bfu(h0) | ((unsigned)bfu(h1) << 16);
    lo = (unsigned)bfu(__float2bfloat16(r0)) |
         ((unsigned)bfu(__float2bfloat16(r1)) << 16);
}

// final rowptr with folded block offset
__device__ __forceinline__ int rp(int i) {
    return (i >= NN) ? NE : g_rowptr[i] + g_boff[i >> 10];
}

// ---------------- index decode --------------------------------------------------
__device__ __forceinline__ int load_idx(const void* p, long long pos) {
    int v;
    if (g_is64) v = (int)((const long long*)p)[pos];
    else        v = ((const int*)p)[pos];
    return min(max(v, 0), NN - 1);
}

// ---------------- fused setup: detect + zero + weight prep + x convert ----------
__global__ void setup_kernel(const void* __restrict__ eidx,
                             const float* __restrict__ x,
                             const float* __restrict__ W1l, const float* __restrict__ W1r,
                             const float* __restrict__ W2l, const float* __restrict__ W2r,
                             const float* __restrict__ Wc1)
{
    long long gid = (long long)blockIdx.x * blockDim.x + threadIdx.x;
    if (gid == 0) {
        const int* w = (const int*)eidx;
        int is64 = 1;
        for (int i = 1; i < 256; i += 2)
            if (w[i] != 0) { is64 = 0; break; }
        g_is64 = is64;
    }
    if (gid < NN) { g_deg[gid] = 0; g_cursor[gid] = 0; }

    long long wI = gid - NN;
    if (wI >= 0 && wI < 98304) {
        float v;
        if (wI < 32768) {
            int n = (int)(wI >> 8), k = (int)(wI & 255);
            v = (k < 128) ? W1l[k * 128 + n] : W1r[(k - 128) * 128 + n];
        } else if (wI < 65536) {
            long long l = wI - 32768;
            int n = (int)(l >> 8), k = (int)(l & 255);
            v = (k < 128) ? W2l[k * 128 + n] : W2r[(k - 128) * 128 + n];
        } else {
            long long l = wI - 65536;
            int n = (int)(l >> 7);            // 0..255 output col
            int k = (int)(l & 127);
            v = Wc1[(size_t)k * 128 + (n & 127) + (n >> 7) * 0];
            // careful: col n in [0,256): weight row of Wc1 half = (n<128? n : n-128),
            // Wc1 half base = (n<128? 0 : 128*128)
            v = (n < 128) ? Wc1[(size_t)k * 128 + n]
                          : Wc1[(size_t)(128 + k) * 128 + (n - 128)];
        }
        __nv_bfloat16 h = __float2bfloat16(v);
        g_wt_hi[wI] = h;
        g_wt_lo[wI] = __float2bfloat16(v - __bfloat162float(h));
    }

    long long cI = gid - NN - 98304;   // x convert: one float4 per thread
    if (cI >= 0 && cI < (long long)NN * 32) {
        float4 v = *(const float4*)(x + cI * 4);
        uint2 hi, lo;
        split4(v, hi, lo);
        *(uint2*)(g_xhi + cI * 4) = hi;
        *(uint2*)(g_xlo + cI * 4) = lo;
        __half2 f01 = __floats2half2_rn(v.x, v.y);
        __half2 f23 = __floats2half2_rn(v.z, v.w);
        uint2 pk;
        pk.x = *(unsigned*)&f01;
        pk.y = *(unsigned*)&f23;
        *(uint2*)(g_x16 + cI * 4) = pk;
    }
}

// ---------------- CSR build ------------------------------------------------------
__global__ void hist_kernel(const void* __restrict__ eidx) {
    int e = blockIdx.x * blockDim.x + threadIdx.x;
    if (e < NE) atomicAdd(&g_deg[load_idx(eidx, (long long)NE + e)], 1);
}

__global__ void scanA_kernel() {
    __shared__ int warp_sums[32];
    int b = blockIdx.x, t = threadIdx.x;
    int i = b * 1024 + t;
    int lane = t & 31, w = t >> 5;
    int v = (i < NN) ? g_deg[i] : 0;
    int s = v;
#pragma unroll
    for (int off = 1; off < 32; off <<= 1) {
        int n = __shfl_up_sync(0xFFFFFFFFu, s, off);
        if (lane >= off) s += n;
    }
    if (lane == 31) warp_sums[w] = s;
    __syncthreads();
    if (w == 0) {
        int ws = warp_sums[lane];
#pragma unroll
        for (int off = 1; off < 32; off <<= 1) {
            int n = __shfl_up_sync(0xFFFFFFFFu, ws, off);
            if (lane >= off) ws += n;
        }
        warp_sums[lane] = ws;
    }
    __syncthreads();
    int woff = (w == 0) ? 0 : warp_sums[w - 1];
    int incl = s + woff;
    if (i < NN) g_rowptr[i] = incl - v;
    if (t == 1023) g_bsum[b] = incl;
}

__global__ void scanB_kernel(int nblocks) {
    __shared__ int sh[64];
    int t = threadIdx.x;
    int v = (t < nblocks) ? g_bsum[t] : 0;
    sh[t] = v;
    __syncthreads();
    for (int off = 1; off < 64; off <<= 1) {
        int n = (t >= off) ? sh[t - off] : 0;
        __syncthreads();
        sh[t] += n;
        __syncthreads();
    }
    g_boff[t] = sh[t] - v;
    if (t == 0) g_rowptr[NN] = NE;
}

__global__ void scatter_kernel(const void* __restrict__ eidx) {
    int e = blockIdx.x * blockDim.x + threadIdx.x;
    if (e < NE) {
        int d = load_idx(eidx, (long long)NE + e);
        int pos = rp(d) + atomicAdd(&g_cursor[d], 1);
        if (pos >= 0 && pos < NE) g_csrc[pos] = load_idx(eidx, e);
    }
}

// ---------------- segment mean: warp per node, x4-unrolled fp16 gather -----------
template <int WHICH>   // 0: gather g_x16, 1: gather g_h1h16
__global__ void aggregate_kernel() {
    const __half* __restrict__ p = (WHICH == 0) ? g_x16 : g_h1h16;
    int gw   = (blockIdx.x * blockDim.x + threadIdx.x) >> 5;
    int lane = threadIdx.x & 31;
    if (gw >= NN) return;
    int r0 = rp(gw);
    int r1 = rp(gw + 1);
    float4 acc = make_float4(0.f, 0.f, 0.f, 0.f);
    int i = r0;
    for (; i + 4 <= r1; i += 4) {
        int s0 = g_csrc[i + 0], s1 = g_csrc[i + 1];
        int s2 = g_csrc[i + 2], s3 = g_csrc[i + 3];
        uint2 v0 = *(const uint2*)(p + (size_t)s0 * F + lane * 4);
        uint2 v1 = *(const uint2*)(p + (size_t)s1 * F + lane * 4);
        uint2 v2 = *(const uint2*)(p + (size_t)s2 * F + lane * 4);
        uint2 v3 = *(const uint2*)(p + (size_t)s3 * F + lane * 4);
        float2 a, b;
        a = __half22float2(*(__half2*)&v0.x); b = __half22float2(*(__half2*)&v0.y);
        acc.x += a.x; acc.y += a.y; acc.z += b.x; acc.w += b.y;
        a = __half22float2(*(__half2*)&v1.x); b = __half22float2(*(__half2*)&v1.y);
        acc.x += a.x; acc.y += a.y; acc.z += b.x; acc.w += b.y;
        a = __half22float2(*(__half2*)&v2.x); b = __half22float2(*(__half2*)&v2.y);
        acc.x += a.x; acc.y += a.y; acc.z += b.x; acc.w += b.y;
        a = __half22float2(*(__half2*)&v3.x); b = __half22float2(*(__half2*)&v3.y);
        acc.x += a.x; acc.y += a.y; acc.z += b.x; acc.w += b.y;
    }
    for (; i < r1; i++) {
        int s = g_csrc[i];
        uint2 v = *(const uint2*)(p + (size_t)s * F + lane * 4);
        float2 a = __half22float2(*(__half2*)&v.x);
        float2 b = __half22float2(*(__half2*)&v.y);
        acc.x += a.x; acc.y += a.y; acc.z += b.x; acc.w += b.y;
    }
    float inv = 1.0f / (float)max(r1 - r0, 1);
    acc.x *= inv; acc.y *= inv; acc.z *= inv; acc.w *= inv;
    uint2 hi, lo;
    split4(acc, hi, lo);
    *(uint2*)(g_mhi + (size_t)gw * F + lane * 4) = hi;
    *(uint2*)(g_mlo + (size_t)gw * F + lane * 4) = lo;
}

// ---------------- HMMA split-bf16 GEMM (conv layers), 128x128 tile ----------------
// MODE 0: h1 = relu(mean@W1 + x@W1r + b)  -> g_h1h16 fp16 + g_h1hi/lo, K=256
// MODE 1: h2 = mean@W2 + h1@W2r + b       -> g_h2hi/lo, K=256
#define SAPAD 40

template <int MODE>
__global__ __launch_bounds__(512)
void mma_gemm(const float* __restrict__ bias, int M)
{
    constexpr int NCHUNK = 8;   // K-chunks of 32, K=256
    constexpr int KTOT   = 256;
    const int wtoff = (MODE == 0) ? 0 : 32768;

    __shared__ __nv_bfloat16 sAhi[128][SAPAD], sAlo[128][SAPAD];
    __shared__ __nv_bfloat16 sBhi[128][SAPAD], sBlo[128][SAPAD];

    int tid  = threadIdx.x;
    int wid  = tid >> 5, lane = tid & 31;
    int m0   = blockIdx.x * 128;
    int wm   = wid >> 2, wn = wid & 3;
    int mb   = wm * 32,  nb = wn * 32;

    float acc[2][4][4];
#pragma unroll
    for (int mi = 0; mi < 2; mi++)
#pragma unroll
        for (int ni = 0; ni < 4; ni++)
#pragma unroll
            for (int q = 0; q < 4; q++) acc[mi][ni][q] = 0.f;

    const int frow = tid >> 2;
    const int fseg = (tid & 3) * 8;
    const int gmf  = m0 + frow;

    const int a_r = (lane & 15);
    const int a_c = (lane >> 4) * 8;
    const int b_r = (lane & 7);
    const int b_c = ((lane >> 3) & 1) * 8;

    for (int ch = 0; ch < NCHUNK; ch++) {
        const __nv_bfloat16 *ah, *al;
        int kk0;
        if (ch < 4)         { ah = g_mhi;  al = g_mlo;  kk0 = ch * 32; }
        else if (MODE == 0) { ah = g_xhi;  al = g_xlo;  kk0 = (ch - 4) * 32; }
        else                { ah = g_h1hi; al = g_h1lo; kk0 = (ch - 4) * 32; }
        int kkw = ch * 32;

        {
            uint4 z = make_uint4(0, 0, 0, 0);
            uint4 vh = z, vl = z;
            if (gmf < M) {
                vh = *(const uint4*)(ah + (size_t)gmf * F + kk0 + fseg);
                vl = *(const uint4*)(al + (size_t)gmf * F + kk0 + fseg);
            }
            *(uint4*)&sAhi[frow][fseg] = vh;
            *(uint4*)&sAlo[frow][fseg] = vl;
            *(uint4*)&sBhi[frow][fseg] =
                *(const uint4*)(g_wt_hi + wtoff + (size_t)frow * KTOT + kkw + fseg);
            *(uint4*)&sBlo[frow][fseg] =
                *(const uint4*)(g_wt_lo + wtoff + (size_t)frow * KTOT + kkw + fseg);
        }
        __syncthreads();

#pragma unroll
        for (int ks = 0; ks < 2; ks++) {
            uint32_t ahf[2][4], alf[2][4], bhf[4][2], blf[4][2];
#pragma unroll
            for (int mi = 0; mi < 2; mi++) {
                ldm_x4(ahf[mi], sm32(&sAhi[mb + mi * 16 + a_r][ks * 16 + a_c]));
                ldm_x4(alf[mi], sm32(&sAlo[mb + mi * 16 + a_r][ks * 16 + a_c]));
            }
#pragma unroll
            for (int ni = 0; ni < 4; ni++) {
                ldm_x2(bhf[ni], sm32(&sBhi[nb + ni * 8 + b_r][ks * 16 + b_c]));
                ldm_x2(blf[ni], sm32(&sBlo[nb + ni * 8 + b_r][ks * 16 + b_c]));
            }
#pragma unroll
            for (int mi = 0; mi < 2; mi++)
#pragma unroll
                for (int ni = 0; ni < 4; ni++) {
                    mma16816(acc[mi][ni], ahf[mi], bhf[ni]);
                    mma16816(acc[mi][ni], ahf[mi], blf[ni]);
                    mma16816(acc[mi][ni], alf[mi], bhf[ni]);
                }
        }
        __syncthreads();
    }

    const int trow = lane >> 2;
    const int tcol = (lane & 3) * 2;
#pragma unroll
    for (int mi = 0; mi < 2; mi++) {
#pragma unroll
        for (int half = 0; half < 2; half++) {
            int m = m0 + mb + mi * 16 + trow + half * 8;
            if (m >= M) continue;
#pragma unroll
            for (int ni = 0; ni < 4; ni++) {
                int col = nb + ni * 8 + tcol;
                float vx = acc[mi][ni][half * 2 + 0];
                float vy = acc[mi][ni][half * 2 + 1];
                vx += bias[col]; vy += bias[col + 1];
                if (MODE == 0) { vx = fmaxf(vx, 0.f); vy = fmaxf(vy, 0.f); }
                if (MODE == 0) {
                    __half2 f = __floats2half2_rn(vx, vy);
                    *(__half2*)(g_h1h16 + (size_t)m * F + col) = f;
                    unsigned hi, lo;
                    split2(vx, vy, hi, lo);
                    *(unsigned*)(g_h1hi + (size_t)m * F + col) = hi;
                    *(unsigned*)(g_h1lo + (size_t)m * F + col) = lo;
                } else {
                    unsigned hi, lo;
                    split2(vx, vy, hi, lo);
                    *(unsigned*)(g_h2hi + (size_t)m * F + col) = hi;
                    *(unsigned*)(g_h2lo + (size_t)m * F + col) = lo;
                }
            }
        }
    }
}

// ---------------- HMMA split-bf16 GEMM, edge pre-projection: 128x256 tile ---------
// ABh[m][0:256] = h2 @ wtc (256 output cols), K=128
__global__ __launch_bounds__(512)
void mma_gemm_ab(int M)
{
    constexpr int KTOT = 128;
    extern __shared__ __nv_bfloat16 smem[];
    // layout: Ahi[128][40], Alo[128][40], Bhi[256][40], Blo[256][40]
    __nv_bfloat16* sAhi = smem;
    __nv_bfloat16* sAlo = sAhi + 128 * SAPAD;
    __nv_bfloat16* sBhi = sAlo + 128 * SAPAD;
    __nv_bfloat16* sBlo = sBhi + 256 * SAPAD;

    int tid  = threadIdx.x;
    int wid  = tid >> 5, lane = tid & 31;
    int m0   = blockIdx.x * 128;
    int wm   = wid >> 2, wn = wid & 3;     // 4x4 warps; each warp 32 rows x 64 cols
    int mb   = wm * 32,  nb = wn * 64;

    float acc[2][8][4];
#pragma unroll
    for (int mi = 0; mi < 2; mi++)
#pragma unroll
        for (int ni = 0; ni < 8; ni++)
#pragma unroll
            for (int q = 0; q < 4; q++) acc[mi][ni][q] = 0.f;

    const int frow = tid >> 2;             // 0..127 (A fill)
    const int fseg = (tid & 3) * 8;
    const int gmf  = m0 + frow;
    const int brow = tid >> 1;             // 0..255 (B fill)
    const int bseg = (tid & 1) * 16;       // two uint4 per thread row (cols 0..31)

    const int a_r = (lane & 15);
    const int a_c = (lane >> 4) * 8;
    const int b_r = (lane & 7);
    const int b_c = ((lane >> 3) & 1) * 8;

    for (int ch = 0; ch < 4; ch++) {       // K chunks of 32
        int kk = ch * 32;
        {
            uint4 z = make_uint4(0, 0, 0, 0);
            uint4 vh = z, vl = z;
            if (gmf < M) {
                vh = *(const uint4*)(g_h2hi + (size_t)gmf * F + kk + fseg);
                vl = *(const uint4*)(g_h2lo + (size_t)gmf * F + kk + fseg);
            }
            *(uint4*)&sAhi[frow * SAPAD + fseg] = vh;
            *(uint4*)&sAlo[frow * SAPAD + fseg] = vl;
            // B: rows 0..255 of wtc
            const __nv_bfloat16* bh = g_wt_hi + 65536 + (size_t)brow * KTOT + kk + bseg;
            const __nv_bfloat16* bl = g_wt_lo + 65536 + (size_t)brow * KTOT + kk + bseg;
            *(uint4*)&sBhi[brow * SAPAD + bseg]     = *(const uint4*)bh;
            *(uint4*)&sBhi[brow * SAPAD + bseg + 8] = *(const uint4*)(bh + 8);
            *(uint4*)&sBlo[brow * SAPAD + bseg]     = *(const uint4*)bl;
            *(uint4*)&sBlo[brow * SAPAD + bseg + 8] = *(const uint4*)(bl + 8);
        }
        __syncthreads();

#pragma unroll
        for (int ks = 0; ks < 2; ks++) {
            uint32_t ahf[2][4], alf[2][4], bhf[8][2], blf[8][2];
#pragma unroll
            for (int mi = 0; mi < 2; mi++) {
                ldm_x4(ahf[mi], sm32(&sAhi[(mb + mi * 16 + a_r) * SAPAD + ks * 16 + a_c]));
                ldm_x4(alf[mi], sm32(&sAlo[(mb + mi * 16 + a_r) * SAPAD + ks * 16 + a_c]));
            }
#pragma unroll
            for (int ni = 0; ni < 8; ni++) {
                ldm_x2(bhf[ni], sm32(&sBhi[(nb + ni * 8 + b_r) * SAPAD + ks * 16 + b_c]));
                ldm_x2(blf[ni], sm32(&sBlo[(nb + ni * 8 + b_r) * SAPAD + ks * 16 + b_c]));
            }
#pragma unroll
            for (int mi = 0; mi < 2; mi++)
#pragma unroll
                for (int ni = 0; ni < 8; ni++) {
                    mma16816(acc[mi][ni], ahf[mi], bhf[ni]);
                    mma16816(acc[mi][ni], ahf[mi], blf[ni]);
                    mma16816(acc[mi][ni], alf[mi], bhf[ni]);
                }
        }
        __syncthreads();
    }

    const int trow = lane >> 2;
    const int tcol = (lane & 3) * 2;
#pragma unroll
    for (int mi = 0; mi < 2; mi++) {
#pragma unroll
        for (int half = 0; half < 2; half++) {
            int m = m0 + mb + mi * 16 + trow + half * 8;
            if (m >= M) continue;
#pragma unroll
            for (int ni = 0; ni < 8; ni++) {
                int col = nb + ni * 8 + tcol;
                __half2 h = __floats2half2_rn(acc[mi][ni][half * 2 + 0],
                                              acc[mi][ni][half * 2 + 1]);
                *(__half2*)(g_ABh + (size_t)m * 256 + col) = h;
            }
        }
    }
}

// ---------------- edge classifier: warp per edge (fp16 AB table) -----------------
__global__ __launch_bounds__(256)
void edge_kernel(const void* __restrict__ eidx,
                 const float* __restrict__ ea,
                 const float* __restrict__ Wc1,
                 const float* __restrict__ bc1,
                 const float* __restrict__ Wc2,
                 const float* __restrict__ bc2,
                 float* __restrict__ out)
{
    __shared__ float sWe0[128], sWe1[128], sWe2[128], sb[128], sw2[128];
    int tid = threadIdx.x;
    if (tid < 128) {
        sWe0[tid] = Wc1[256 * 128 + tid];
        sWe1[tid] = Wc1[257 * 128 + tid];
        sWe2[tid] = Wc1[258 * 128 + tid];
        sb[tid]   = bc1[tid];
        sw2[tid]  = Wc2[tid];
    }
    __syncthreads();

    int e = blockIdx.x * (blockDim.x >> 5) + (tid >> 5);
    if (e >= NE) return;
    int lane = tid & 31;
    int j = lane * 4;

    int s = load_idx(eidx, e);
    int d = load_idx(eidx, (long long)NE + e);

    uint2 av = *(const uint2*)(g_ABh + (size_t)s * 256 + j);
    uint2 bv = *(const uint2*)(g_ABh + (size_t)d * 256 + 128 + j);
    float2 a01 = __half22float2(*(__half2*)&av.x);
    float2 a23 = __half22float2(*(__half2*)&av.y);
    float2 b01 = __half22float2(*(__half2*)&bv.x);
    float2 b23 = __half22float2(*(__half2*)&bv.y);

    float4 w0 = *(const float4*)&sWe0[j];
    float4 w1 = *(const float4*)&sWe1[j];
    float4 w2 = *(const float4*)&sWe2[j];
    float4 bb = *(const float4*)&sb[j];
    float4 wc = *(const float4*)&sw2[j];

    float e0 = ea[(size_t)e * 3 + 0];
    float e1 = ea[(size_t)e * 3 + 1];
    float e2 = ea[(size_t)e * 3 + 2];

    float h, acc = 0.f;
    h = a01.x + b01.x + e0 * w0.x + e1 * w1.x + e2 * w2.x + bb.x;
    acc += fmaxf(h, 0.f) * wc.x;
    h = a01.y + b01.y + e0 * w0.y + e1 * w1.y + e2 * w2.y + bb.y;
    acc += fmaxf(h, 0.f) * wc.y;
    h = a23.x + b23.x + e0 * w0.z + e1 * w1.z + e2 * w2.z + bb.z;
    acc += fmaxf(h, 0.f) * wc.z;
    h = a23.y + b23.y + e0 * w0.w + e1 * w1.w + e2 * w2.w + bb.w;
    acc += fmaxf(h, 0.f) * wc.w;

#pragma unroll
    for (int off = 16; off > 0; off >>= 1)
        acc += __shfl_xor_sync(0xFFFFFFFFu, acc, off);

    if (lane == 0) out[e] = acc + bc2[0];
}

// ---------------- launch -----------------------------------------------------------
extern "C" void kernel_launch(void* const* d_in, const int* in_sizes, int n_in,
                              void* d_out, int out_size)
{
    const float* x    = (const float*)d_in[0];
    const void*  eidx = d_in[1];
    const float* ea   = (const float*)d_in[2];
    const float* W1l  = (const float*)d_in[3];
    const float* b1l  = (const float*)d_in[4];
    const float* W1r  = (const float*)d_in[5];
    const float* W2l  = (const float*)d_in[6];
    const float* b2l  = (const float*)d_in[7];
    const float* W2r  = (const float*)d_in[8];
    const float* Wc1  = (const float*)d_in[9];
    const float* bc1  = (const float*)d_in[10];
    const float* Wc2  = (const float*)d_in[11];
    const float* bc2  = (const float*)d_in[12];
    float* out = (float*)d_out;

    const int SCAN_BLOCKS = (NN + 1023) / 1024;  // 49
    const int AB_SMEM = (128 * SAPAD * 2 + 256 * SAPAD * 2) * (int)sizeof(__nv_bfloat16);

    static int attr_done = 0;
    // (setting a func attribute is idempotent and not a stream op; safe every call)
    cudaFuncSetAttribute(mma_gemm_ab, cudaFuncAttributeMaxDynamicSharedMemorySize, AB_SMEM);
    (void)attr_done;

    long long setup_threads = (long long)NN + 98304 + (long long)NN * 32;
    int setup_grid = (int)((setup_threads + 255) / 256);
    setup_kernel<<<setup_grid, 256>>>(eidx, x, W1l, W1r, W2l, W2r, Wc1);

    hist_kernel<<<(NE + 255) / 256, 256>>>(eidx);
    scanA_kernel<<<SCAN_BLOCKS, 1024>>>();
    scanB_kernel<<<1, 64>>>(SCAN_BLOCKS);
    scatter_kernel<<<(NE + 255) / 256, 256>>>(eidx);

    const int aggGrid  = (NN * 32 + 255) / 256;
    const int gemmGrid = (NN + 127) / 128;       // 391

    aggregate_kernel<0><<<aggGrid, 256>>>();
    mma_gemm<0><<<gemmGrid, 512>>>(b1l, NN);

    aggregate_kernel<1><<<aggGrid, 256>>>();
    mma_gemm<1><<<gemmGrid, 512>>>(b2l, NN);

    mma_gemm_ab<<<gemmGrid, 512, AB_SMEM>>>(NN);

    edge_kernel<<<(NE * 32 + 255) / 256, 256>>>(eidx, ea, Wc1, bc1, Wc2, bc2, out);
}

// round 10
// speedup vs baseline: 1.0663x; 1.0663x over previous
#include <cuda_runtime.h>
#include <cuda_fp16.h>
#include <cuda_bf16.h>
#include <cstdint>

#define NN 50000
#define NE 800000
#define F  128

// ---------------- scratch (static device globals) ---------------------------
__device__ __align__(16) int    g_deg[NN];
__device__ __align__(16) int    g_cursor[NN];
__device__ __align__(16) int    g_rowptr[NN + 1];   // block-local exclusive scan
__device__ __align__(16) int    g_csrc[NE];
__device__ __align__(16) __half g_ABh[(size_t)NN * 256];
__device__ __align__(16) int    g_bsum[64];
__device__ __align__(16) int    g_boff[64];
__device__ int g_is64;

// fp16 activation tables (single copy; split to bf16 hi/lo on-the-fly in GEMM fill)
__device__ __align__(16) __half g_x16[NN * F];
__device__ __align__(16) __half g_m16[NN * F];
__device__ __align__(16) __half g_h1h16[NN * F];
__device__ __align__(16) __half g_h2h16[NN * F];
// weights transposed+split: wt[n][k]; wt1 @0 (K=256), wt2 @32768 (K=256),
// wtc @65536 (two 128x128 halves, half by: base 65536 + by*16384)
__device__ __align__(16) __nv_bfloat16 g_wt_hi[98304], g_wt_lo[98304];

// ---------------- helpers -----------------------------------------------------
__device__ __forceinline__ uint32_t sm32(const void* p) {
    uint32_t a;
    asm("{ .reg .u64 t; cvta.to.shared.u64 t, %1; cvt.u32.u64 %0, t; }"
        : "=r"(a) : "l"(p));
    return a;
}

__device__ __forceinline__ void ldm_x4(uint32_t (&r)[4], uint32_t addr) {
    asm volatile("ldmatrix.sync.aligned.m8n8.x4.shared.b16 {%0,%1,%2,%3}, [%4];"
        : "=r"(r[0]), "=r"(r[1]), "=r"(r[2]), "=r"(r[3]) : "r"(addr));
}
__device__ __forceinline__ void ldm_x2(uint32_t (&r)[2], uint32_t addr) {
    asm volatile("ldmatrix.sync.aligned.m8n8.x2.shared.b16 {%0,%1}, [%2];"
        : "=r"(r[0]), "=r"(r[1]) : "r"(addr));
}
__device__ __forceinline__ void mma16816(float (&d)[4], const uint32_t (&a)[4],
                                         const uint32_t (&b)[2]) {
    asm volatile("mma.sync.aligned.m16n8k16.row.col.f32.bf16.bf16.f32 "
        "{%0,%1,%2,%3}, {%4,%5,%6,%7}, {%8,%9}, {%0,%1,%2,%3};"
        : "+f"(d[0]), "+f"(d[1]), "+f"(d[2]), "+f"(d[3])
        : "r"(a[0]), "r"(a[1]), "r"(a[2]), "r"(a[3]), "r"(b[0]), "r"(b[1]));
}

__device__ __forceinline__ unsigned short bfu(__nv_bfloat16 h) {
    return __bfloat16_as_ushort(h);
}
// 8x fp16 -> 8x (bf16 hi, bf16 lo); exact (fp16 mantissa fits in hi+lo)
__device__ __forceinline__ void cvt8(uint4 vin, uint4& hi, uint4& lo) {
    const __half* hp = (const __half*)&vin;
    unsigned* hu = (unsigned*)&hi;
    unsigned* lu = (unsigned*)&lo;
#pragma unroll
    for (int i = 0; i < 4; i++) {
        float f0 = __half2float(hp[2 * i]);
        float f1 = __half2float(hp[2 * i + 1]);
        __nv_bfloat16 h0 = __float2bfloat16(f0);
        __nv_bfloat16 h1 = __float2bfloat16(f1);
        __nv_bfloat16 l0 = __float2bfloat16(f0 - __bfloat162float(h0));
        __nv_bfloat16 l1 = __float2bfloat16(f1 - __bfloat162float(h1));
        hu[i] = (unsigned)bfu(h0) | ((unsigned)bfu(h1) << 16);
        lu[i] = (unsigned)bfu(l0) | ((unsigned)bfu(l1) << 16);
    }
}

// final rowptr with folded block offset
__device__ __forceinline__ int rp(int i) {
    return (i >= NN) ? NE : g_rowptr[i] + g_boff[i >> 10];
}

// ---------------- index decode --------------------------------------------------
__device__ __forceinline__ int load_idx(const void* p, long long pos) {
    int v;
    if (g_is64) v = (int)((const long long*)p)[pos];
    else        v = ((const int*)p)[pos];
    return min(max(v, 0), NN - 1);
}

// ---------------- fused setup: detect + zero + weight prep + x convert ----------
__global__ void setup_kernel(const void* __restrict__ eidx,
                             const float* __restrict__ x,
                             const float* __restrict__ W1l, const float* __restrict__ W1r,
                             const float* __restrict__ W2l, const float* __restrict__ W2r,
                             const float* __restrict__ Wc1)
{
    long long gid = (long long)blockIdx.x * blockDim.x + threadIdx.x;
    if (gid == 0) {
        const int* w = (const int*)eidx;
        int is64 = 1;
        for (int i = 1; i < 256; i += 2)
            if (w[i] != 0) { is64 = 0; break; }
        g_is64 = is64;
    }
    if (gid < NN) { g_deg[gid] = 0; g_cursor[gid] = 0; }

    long long wI = gid - NN;
    if (wI >= 0 && wI < 98304) {
        float v;
        if (wI < 32768) {
            int n = (int)(wI >> 8), k = (int)(wI & 255);
            v = (k < 128) ? W1l[k * 128 + n] : W1r[(k - 128) * 128 + n];
        } else if (wI < 65536) {
            long long l = wI - 32768;
            int n = (int)(l >> 8), k = (int)(l & 255);
            v = (k < 128) ? W2l[k * 128 + n] : W2r[(k - 128) * 128 + n];
        } else {
            long long l = wI - 65536;
            int by = (int)(l >> 14), r = (int)(l & 16383);
            int n = r >> 7, k = r & 127;
            v = Wc1[(size_t)(by * 128 + k) * 128 + n];
        }
        __nv_bfloat16 h = __float2bfloat16(v);
        g_wt_hi[wI] = h;
        g_wt_lo[wI] = __float2bfloat16(v - __bfloat162float(h));
    }

    long long cI = gid - NN - 98304;   // x convert: one float4 per thread
    if (cI >= 0 && cI < (long long)NN * 32) {
        float4 v = *(const float4*)(x + cI * 4);
        __half2 f01 = __floats2half2_rn(v.x, v.y);
        __half2 f23 = __floats2half2_rn(v.z, v.w);
        uint2 pk;
        pk.x = *(unsigned*)&f01;
        pk.y = *(unsigned*)&f23;
        *(uint2*)(g_x16 + cI * 4) = pk;
    }
}

// ---------------- CSR build ------------------------------------------------------
__global__ void hist_kernel(const void* __restrict__ eidx) {
    int e = blockIdx.x * blockDim.x + threadIdx.x;
    if (e < NE) atomicAdd(&g_deg[load_idx(eidx, (long long)NE + e)], 1);
}

__global__ void scanA_kernel() {
    __shared__ int warp_sums[32];
    int b = blockIdx.x, t = threadIdx.x;
    int i = b * 1024 + t;
    int lane = t & 31, w = t >> 5;
    int v = (i < NN) ? g_deg[i] : 0;
    int s = v;
#pragma unroll
    for (int off = 1; off < 32; off <<= 1) {
        int n = __shfl_up_sync(0xFFFFFFFFu, s, off);
        if (lane >= off) s += n;
    }
    if (lane == 31) warp_sums[w] = s;
    __syncthreads();
    if (w == 0) {
        int ws = warp_sums[lane];
#pragma unroll
        for (int off = 1; off < 32; off <<= 1) {
            int n = __shfl_up_sync(0xFFFFFFFFu, ws, off);
            if (lane >= off) ws += n;
        }
        warp_sums[lane] = ws;
    }
    __syncthreads();
    int woff = (w == 0) ? 0 : warp_sums[w - 1];
    int incl = s + woff;
    if (i < NN) g_rowptr[i] = incl - v;
    if (t == 1023) g_bsum[b] = incl;
}

__global__ void scanB_kernel(int nblocks) {
    __shared__ int sh[64];
    int t = threadIdx.x;
    int v = (t < nblocks) ? g_bsum[t] : 0;
    sh[t] = v;
    __syncthreads();
    for (int off = 1; off < 64; off <<= 1) {
        int n = (t >= off) ? sh[t - off] : 0;
        __syncthreads();
        sh[t] += n;
        __syncthreads();
    }
    g_boff[t] = sh[t] - v;
    if (t == 0) g_rowptr[NN] = NE;
}

__global__ void scatter_kernel(const void* __restrict__ eidx) {
    int e = blockIdx.x * blockDim.x + threadIdx.x;
    if (e < NE) {
        int d = load_idx(eidx, (long long)NE + e);
        int pos = rp(d) + atomicAdd(&g_cursor[d], 1);
        if (pos >= 0 && pos < NE) g_csrc[pos] = load_idx(eidx, e);
    }
}

// ---------------- segment mean: warp per node, x4-unrolled fp16 gather -----------
template <int WHICH>   // 0: gather g_x16, 1: gather g_h1h16
__global__ void aggregate_kernel() {
    const __half* __restrict__ p = (WHICH == 0) ? g_x16 : g_h1h16;
    int gw   = (blockIdx.x * blockDim.x + threadIdx.x) >> 5;
    int lane = threadIdx.x & 31;
    if (gw >= NN) return;
    int r0 = rp(gw);
    int r1 = rp(gw + 1);
    float4 acc = make_float4(0.f, 0.f, 0.f, 0.f);
    int i = r0;
    for (; i + 4 <= r1; i += 4) {
        int s0 = g_csrc[i + 0], s1 = g_csrc[i + 1];
        int s2 = g_csrc[i + 2], s3 = g_csrc[i + 3];
        uint2 v0 = *(const uint2*)(p + (size_t)s0 * F + lane * 4);
        uint2 v1 = *(const uint2*)(p + (size_t)s1 * F + lane * 4);
        uint2 v2 = *(const uint2*)(p + (size_t)s2 * F + lane * 4);
        uint2 v3 = *(const uint2*)(p + (size_t)s3 * F + lane * 4);
        float2 a, b;
        a = __half22float2(*(__half2*)&v0.x); b = __half22float2(*(__half2*)&v0.y);
        acc.x += a.x; acc.y += a.y; acc.z += b.x; acc.w += b.y;
        a = __half22float2(*(__half2*)&v1.x); b = __half22float2(*(__half2*)&v1.y);
        acc.x += a.x; acc.y += a.y; acc.z += b.x; acc.w += b.y;
        a = __half22float2(*(__half2*)&v2.x); b = __half22float2(*(__half2*)&v2.y);
        acc.x += a.x; acc.y += a.y; acc.z += b.x; acc.w += b.y;
        a = __half22float2(*(__half2*)&v3.x); b = __half22float2(*(__half2*)&v3.y);
        acc.x += a.x; acc.y += a.y; acc.z += b.x; acc.w += b.y;
    }
    for (; i < r1; i++) {
        int s = g_csrc[i];
        uint2 v = *(const uint2*)(p + (size_t)s * F + lane * 4);
        float2 a = __half22float2(*(__half2*)&v.x);
        float2 b = __half22float2(*(__half2*)&v.y);
        acc.x += a.x; acc.y += a.y; acc.z += b.x; acc.w += b.y;
    }
    float inv = 1.0f / (float)max(r1 - r0, 1);
    __half2 m01 = __floats2half2_rn(acc.x * inv, acc.y * inv);
    __half2 m23 = __floats2half2_rn(acc.z * inv, acc.w * inv);
    uint2 pk;
    pk.x = *(unsigned*)&m01;
    pk.y = *(unsigned*)&m23;
    *(uint2*)(g_m16 + (size_t)gw * F + lane * 4) = pk;
}

// ---------------- HMMA split-bf16 GEMM (fp16 A source, split in fill) -------------
// MODE 0: h1 = relu(mean@W1 + x@W1r + b)  -> g_h1h16 fp16, K=256
// MODE 1: h2 = mean@W2 + h1@W2r + b       -> g_h2h16 fp16, K=256
// MODE 2: ABh[:, by*128..] = h2 @ wtc_by  -> g_ABh fp16, K=128, grid.y=2
#define SAPAD 40

template <int MODE>
__global__ __launch_bounds__(512)
void mma_gemm(const float* __restrict__ bias, int M)
{
    constexpr int NCHUNK = (MODE <= 1) ? 8 : 4;   // K-chunks of 32
    constexpr int KTOT   = (MODE <= 1) ? 256 : 128;
    const int wtoff = (MODE == 0) ? 0 : (MODE == 1) ? 32768
                     : 65536 + (int)blockIdx.y * 16384;

    __shared__ __nv_bfloat16 sAhi[128][SAPAD], sAlo[128][SAPAD];
    __shared__ __nv_bfloat16 sBhi[128][SAPAD], sBlo[128][SAPAD];

    int tid  = threadIdx.x;
    int wid  = tid >> 5, lane = tid & 31;
    int m0   = blockIdx.x * 128;
    int wm   = wid >> 2, wn = wid & 3;
    int mb   = wm * 32,  nb = wn * 32;

    float acc[2][4][4];
#pragma unroll
    for (int mi = 0; mi < 2; mi++)
#pragma unroll
        for (int ni = 0; ni < 4; ni++)
#pragma unroll
            for (int q = 0; q < 4; q++) acc[mi][ni][q] = 0.f;

    const int frow = tid >> 2;            // 0..127
    const int fseg = (tid & 3) * 8;       // 0,8,16,24 (elems)
    const int gmf  = m0 + frow;

    const int a_r = (lane & 15);
    const int a_c = (lane >> 4) * 8;
    const int b_r = (lane & 7);
    const int b_c = ((lane >> 3) & 1) * 8;

    for (int ch = 0; ch < NCHUNK; ch++) {
        const __half* a16;
        int kk0;
        if (MODE == 2)      { a16 = g_h2h16; kk0 = ch * 32; }
        else if (ch < 4)    { a16 = g_m16;   kk0 = ch * 32; }
        else if (MODE == 0) { a16 = g_x16;   kk0 = (ch - 4) * 32; }
        else                { a16 = g_h1h16; kk0 = (ch - 4) * 32; }
        int kkw = ch * 32;

        {
            uint4 vh = make_uint4(0, 0, 0, 0), vl = make_uint4(0, 0, 0, 0);
            if (gmf < M) {
                uint4 v16 = *(const uint4*)(a16 + (size_t)gmf * F + kk0 + fseg);
                cvt8(v16, vh, vl);
            }
            *(uint4*)&sAhi[frow][fseg] = vh;
            *(uint4*)&sAlo[frow][fseg] = vl;
            *(uint4*)&sBhi[frow][fseg] =
                *(const uint4*)(g_wt_hi + wtoff + (size_t)frow * KTOT + kkw + fseg);
            *(uint4*)&sBlo[frow][fseg] =
                *(const uint4*)(g_wt_lo + wtoff + (size_t)frow * KTOT + kkw + fseg);
        }
        __syncthreads();

#pragma unroll
        for (int ks = 0; ks < 2; ks++) {
            uint32_t ahf[2][4], alf[2][4], bhf[4][2], blf[4][2];
#pragma unroll
            for (int mi = 0; mi < 2; mi++) {
                ldm_x4(ahf[mi], sm32(&sAhi[mb + mi * 16 + a_r][ks * 16 + a_c]));
                ldm_x4(alf[mi], sm32(&sAlo[mb + mi * 16 + a_r][ks * 16 + a_c]));
            }
#pragma unroll
            for (int ni = 0; ni < 4; ni++) {
                ldm_x2(bhf[ni], sm32(&sBhi[nb + ni * 8 + b_r][ks * 16 + b_c]));
                ldm_x2(blf[ni], sm32(&sBlo[nb + ni * 8 + b_r][ks * 16 + b_c]));
            }
#pragma unroll
            for (int mi = 0; mi < 2; mi++)
#pragma unroll
                for (int ni = 0; ni < 4; ni++) {
                    mma16816(acc[mi][ni], ahf[mi], bhf[ni]);
                    mma16816(acc[mi][ni], ahf[mi], blf[ni]);
                    mma16816(acc[mi][ni], alf[mi], bhf[ni]);
                }
        }
        __syncthreads();
    }

    const int trow = lane >> 2;
    const int tcol = (lane & 3) * 2;
#pragma unroll
    for (int mi = 0; mi < 2; mi++) {
#pragma unroll
        for (int half = 0; half < 2; half++) {
            int m = m0 + mb + mi * 16 + trow + half * 8;
            if (m >= M) continue;
#pragma unroll
            for (int ni = 0; ni < 4; ni++) {
                int col = nb + ni * 8 + tcol;
                float vx = acc[mi][ni][half * 2 + 0];
                float vy = acc[mi][ni][half * 2 + 1];
                if (MODE <= 1) { vx += bias[col]; vy += bias[col + 1]; }
                if (MODE == 0) { vx = fmaxf(vx, 0.f); vy = fmaxf(vy, 0.f); }
                __half2 h = __floats2half2_rn(vx, vy);
                if (MODE == 0) {
                    *(__half2*)(g_h1h16 + (size_t)m * F + col) = h;
                } else if (MODE == 1) {
                    *(__half2*)(g_h2h16 + (size_t)m * F + col) = h;
                } else {
                    *(__half2*)(g_ABh + (size_t)m * 256 + blockIdx.y * 128 + col) = h;
                }
            }
        }
    }
}

// ---------------- edge classifier: warp per edge (fp16 AB table) -----------------
__global__ __launch_bounds__(256)
void edge_kernel(const void* __restrict__ eidx,
                 const float* __restrict__ ea,
                 const float* __restrict__ Wc1,
                 const float* __restrict__ bc1,
                 const float* __restrict__ Wc2,
                 const float* __restrict__ bc2,
                 float* __restrict__ out)
{
    __shared__ float sWe0[128], sWe1[128], sWe2[128], sb[128], sw2[128];
    int tid = threadIdx.x;
    if (tid < 128) {
        sWe0[tid] = Wc1[256 * 128 + tid];
        sWe1[tid] = Wc1[257 * 128 + tid];
        sWe2[tid] = Wc1[258 * 128 + tid];
        sb[tid]   = bc1[tid];
        sw2[tid]  = Wc2[tid];
    }
    __syncthreads();

    int e = blockIdx.x * (blockDim.x >> 5) + (tid >> 5);
    if (e >= NE) return;
    int lane = tid & 31;
    int j = lane * 4;

    int s = load_idx(eidx, e);
    int d = load_idx(eidx, (long long)NE + e);

    uint2 av = *(const uint2*)(g_ABh + (size_t)s * 256 + j);
    uint2 bv = *(const uint2*)(g_ABh + (size_t)d * 256 + 128 + j);
    float2 a01 = __half22float2(*(__half2*)&av.x);
    float2 a23 = __half22float2(*(__half2*)&av.y);
    float2 b01 = __half22float2(*(__half2*)&bv.x);
    float2 b23 = __half22float2(*(__half2*)&bv.y);

    float4 w0 = *(const float4*)&sWe0[j];
    float4 w1 = *(const float4*)&sWe1[j];
    float4 w2 = *(const float4*)&sWe2[j];
    float4 bb = *(const float4*)&sb[j];
    float4 wc = *(const float4*)&sw2[j];

    float e0 = ea[(size_t)e * 3 + 0];
    float e1 = ea[(size_t)e * 3 + 1];
    float e2 = ea[(size_t)e * 3 + 2];

    float h, acc = 0.f;
    h = a01.x + b01.x + e0 * w0.x + e1 * w1.x + e2 * w2.x + bb.x;
    acc += fmaxf(h, 0.f) * wc.x;
    h = a01.y + b01.y + e0 * w0.y + e1 * w1.y + e2 * w2.y + bb.y;
    acc += fmaxf(h, 0.f) * wc.y;
    h = a23.x + b23.x + e0 * w0.z + e1 * w1.z + e2 * w2.z + bb.z;
    acc += fmaxf(h, 0.f) * wc.z;
    h = a23.y + b23.y + e0 * w0.w + e1 * w1.w + e2 * w2.w + bb.w;
    acc += fmaxf(h, 0.f) * wc.w;

#pragma unroll
    for (int off = 16; off > 0; off >>= 1)
        acc += __shfl_xor_sync(0xFFFFFFFFu, acc, off);

    if (lane == 0) out[e] = acc + bc2[0];
}

// ---------------- launch -----------------------------------------------------------
extern "C" void kernel_launch(void* const* d_in, const int* in_sizes, int n_in,
                              void* d_out, int out_size)
{
    const float* x    = (const float*)d_in[0];
    const void*  eidx = d_in[1];
    const float* ea   = (const float*)d_in[2];
    const float* W1l  = (const float*)d_in[3];
    const float* b1l  = (const float*)d_in[4];
    const float* W1r  = (const float*)d_in[5];
    const float* W2l  = (const float*)d_in[6];
    const float* b2l  = (const float*)d_in[7];
    const float* W2r  = (const float*)d_in[8];
    const float* Wc1  = (const float*)d_in[9];
    const float* bc1  = (const float*)d_in[10];
    const float* Wc2  = (const float*)d_in[11];
    const float* bc2  = (const float*)d_in[12];
    float* out = (float*)d_out;

    const int SCAN_BLOCKS = (NN + 1023) / 1024;  // 49

    long long setup_threads = (long long)NN + 98304 + (long long)NN * 32;
    int setup_grid = (int)((setup_threads + 255) / 256);
    setup_kernel<<<setup_grid, 256>>>(eidx, x, W1l, W1r, W2l, W2r, Wc1);

    hist_kernel<<<(NE + 255) / 256, 256>>>(eidx);
    scanA_kernel<<<SCAN_BLOCKS, 1024>>>();
    scanB_kernel<<<1, 64>>>(SCAN_BLOCKS);
    scatter_kernel<<<(NE + 255) / 256, 256>>>(eidx);

    const int aggGrid  = (NN * 32 + 255) / 256;
    const int gemmGrid = (NN + 127) / 128;       // 391

    aggregate_kernel<0><<<aggGrid, 256>>>();
    mma_gemm<0><<<gemmGrid, 512>>>(b1l, NN);

    aggregate_kernel<1><<<aggGrid, 256>>>();
    mma_gemm<1><<<gemmGrid, 512>>>(b2l, NN);

    mma_gemm<2><<<dim3(gemmGrid, 2), 512>>>(nullptr, NN);

    edge_kernel<<<(NE * 32 + 255) / 256, 256>>>(eidx, ea, Wc1, bc1, Wc2, bc2, out);
}

// round 11
// speedup vs baseline: 1.2194x; 1.1436x over previous
#include <cuda_runtime.h>
#include <cuda_fp16.h>
#include <cuda_bf16.h>
#include <cstdint>

#define NN 50000
#define NE 800000
#define F  128

// ---------------- scratch (static device globals) ---------------------------
__device__ __align__(16) int    g_deg[NN];
__device__ __align__(16) int    g_cursor[NN];
__device__ __align__(16) int    g_rowptr[NN + 1];   // block-local exclusive scan
__device__ __align__(16) int    g_csrc[NE];
__device__ __align__(16) __half g_ABh[(size_t)NN * 256];
__device__ __align__(16) int    g_bsum[64];
__device__ __align__(16) int    g_boff[64];
__device__ int g_is64;

// fp16 activation tables (exact GEMM A operands)
__device__ __align__(16) __half g_x16[NN * F];
__device__ __align__(16) __half g_m16[NN * F];
__device__ __align__(16) __half g_h1h16[NN * F];
__device__ __align__(16) __half g_h2h16[NN * F];
// weights transposed + fp16 hi/lo split: wt[n][k];
// wt1 @0 (K=256), wt2 @32768 (K=256), wtc @65536 (two 128x128 halves, +by*16384)
__device__ __align__(16) __half g_wt_hi[98304], g_wt_lo[98304];

// ---------------- helpers -----------------------------------------------------
__device__ __forceinline__ uint32_t sm32(const void* p) {
    uint32_t a;
    asm("{ .reg .u64 t; cvta.to.shared.u64 t, %1; cvt.u32.u64 %0, t; }"
        : "=r"(a) : "l"(p));
    return a;
}

__device__ __forceinline__ void ldm_x4(uint32_t (&r)[4], uint32_t addr) {
    asm volatile("ldmatrix.sync.aligned.m8n8.x4.shared.b16 {%0,%1,%2,%3}, [%4];"
        : "=r"(r[0]), "=r"(r[1]), "=r"(r[2]), "=r"(r[3]) : "r"(addr));
}
__device__ __forceinline__ void ldm_x2(uint32_t (&r)[2], uint32_t addr) {
    asm volatile("ldmatrix.sync.aligned.m8n8.x2.shared.b16 {%0,%1}, [%2];"
        : "=r"(r[0]), "=r"(r[1]) : "r"(addr));
}
// fp16 x fp16 -> fp32 MMA
__device__ __forceinline__ void mma16816h(float (&d)[4], const uint32_t (&a)[4],
                                          const uint32_t (&b)[2]) {
    asm volatile("mma.sync.aligned.m16n8k16.row.col.f32.f16.f16.f32 "
        "{%0,%1,%2,%3}, {%4,%5,%6,%7}, {%8,%9}, {%0,%1,%2,%3};"
        : "+f"(d[0]), "+f"(d[1]), "+f"(d[2]), "+f"(d[3])
        : "r"(a[0]), "r"(a[1]), "r"(a[2]), "r"(a[3]), "r"(b[0]), "r"(b[1]));
}

// final rowptr with folded block offset
__device__ __forceinline__ int rp(int i) {
    return (i >= NN) ? NE : g_rowptr[i] + g_boff[i >> 10];
}

// ---------------- index decode --------------------------------------------------
__device__ __forceinline__ int load_idx(const void* p, long long pos) {
    int v;
    if (g_is64) v = (int)((const long long*)p)[pos];
    else        v = ((const int*)p)[pos];
    return min(max(v, 0), NN - 1);
}

// ---------------- fused setup: detect + zero + weight prep + x convert ----------
__global__ void setup_kernel(const void* __restrict__ eidx,
                             const float* __restrict__ x,
                             const float* __restrict__ W1l, const float* __restrict__ W1r,
                             const float* __restrict__ W2l, const float* __restrict__ W2r,
                             const float* __restrict__ Wc1)
{
    long long gid = (long long)blockIdx.x * blockDim.x + threadIdx.x;
    if (gid == 0) {
        const int* w = (const int*)eidx;
        int is64 = 1;
        for (int i = 1; i < 256; i += 2)
            if (w[i] != 0) { is64 = 0; break; }
        g_is64 = is64;
    }
    if (gid < NN) { g_deg[gid] = 0; g_cursor[gid] = 0; }

    long long wI = gid - NN;
    if (wI >= 0 && wI < 98304) {
        float v;
        if (wI < 32768) {
            int n = (int)(wI >> 8), k = (int)(wI & 255);
            v = (k < 128) ? W1l[k * 128 + n] : W1r[(k - 128) * 128 + n];
        } else if (wI < 65536) {
            long long l = wI - 32768;
            int n = (int)(l >> 8), k = (int)(l & 255);
            v = (k < 128) ? W2l[k * 128 + n] : W2r[(k - 128) * 128 + n];
        } else {
            long long l = wI - 65536;
            int by = (int)(l >> 14), r = (int)(l & 16383);
            int n = r >> 7, k = r & 127;
            v = Wc1[(size_t)(by * 128 + k) * 128 + n];
        }
        __half h = __float2half_rn(v);
        g_wt_hi[wI] = h;
        g_wt_lo[wI] = __float2half_rn(v - __half2float(h));
    }

    long long cI = gid - NN - 98304;   // x convert: one float4 per thread
    if (cI >= 0 && cI < (long long)NN * 32) {
        float4 v = *(const float4*)(x + cI * 4);
        __half2 f01 = __floats2half2_rn(v.x, v.y);
        __half2 f23 = __floats2half2_rn(v.z, v.w);
        uint2 pk;
        pk.x = *(unsigned*)&f01;
        pk.y = *(unsigned*)&f23;
        *(uint2*)(g_x16 + cI * 4) = pk;
    }
}

// ---------------- CSR build ------------------------------------------------------
__global__ void hist_kernel(const void* __restrict__ eidx) {
    int e = blockIdx.x * blockDim.x + threadIdx.x;
    if (e < NE) atomicAdd(&g_deg[load_idx(eidx, (long long)NE + e)], 1);
}

__global__ void scanA_kernel() {
    __shared__ int warp_sums[32];
    int b = blockIdx.x, t = threadIdx.x;
    int i = b * 1024 + t;
    int lane = t & 31, w = t >> 5;
    int v = (i < NN) ? g_deg[i] : 0;
    int s = v;
#pragma unroll
    for (int off = 1; off < 32; off <<= 1) {
        int n = __shfl_up_sync(0xFFFFFFFFu, s, off);
        if (lane >= off) s += n;
    }
    if (lane == 31) warp_sums[w] = s;
    __syncthreads();
    if (w == 0) {
        int ws = warp_sums[lane];
#pragma unroll
        for (int off = 1; off < 32; off <<= 1) {
            int n = __shfl_up_sync(0xFFFFFFFFu, ws, off);
            if (lane >= off) ws += n;
        }
        warp_sums[lane] = ws;
    }
    __syncthreads();
    int woff = (w == 0) ? 0 : warp_sums[w - 1];
    int incl = s + woff;
    if (i < NN) g_rowptr[i] = incl - v;
    if (t == 1023) g_bsum[b] = incl;
}

__global__ void scanB_kernel(int nblocks) {
    __shared__ int sh[64];
    int t = threadIdx.x;
    int v = (t < nblocks) ? g_bsum[t] : 0;
    sh[t] = v;
    __syncthreads();
    for (int off = 1; off < 64; off <<= 1) {
        int n = (t >= off) ? sh[t - off] : 0;
        __syncthreads();
        sh[t] += n;
        __syncthreads();
    }
    g_boff[t] = sh[t] - v;
    if (t == 0) g_rowptr[NN] = NE;
}

__global__ void scatter_kernel(const void* __restrict__ eidx) {
    int e = blockIdx.x * blockDim.x + threadIdx.x;
    if (e < NE) {
        int d = load_idx(eidx, (long long)NE + e);
        int pos = rp(d) + atomicAdd(&g_cursor[d], 1);
        if (pos >= 0 && pos < NE) g_csrc[pos] = load_idx(eidx, e);
    }
}

// ---------------- segment mean: warp per node, x4-unrolled fp16 gather -----------
template <int WHICH>   // 0: gather g_x16, 1: gather g_h1h16
__global__ void aggregate_kernel() {
    const __half* __restrict__ p = (WHICH == 0) ? g_x16 : g_h1h16;
    int gw   = (blockIdx.x * blockDim.x + threadIdx.x) >> 5;
    int lane = threadIdx.x & 31;
    if (gw >= NN) return;
    int r0 = rp(gw);
    int r1 = rp(gw + 1);
    float4 acc = make_float4(0.f, 0.f, 0.f, 0.f);
    int i = r0;
    for (; i + 4 <= r1; i += 4) {
        int s0 = g_csrc[i + 0], s1 = g_csrc[i + 1];
        int s2 = g_csrc[i + 2], s3 = g_csrc[i + 3];
        uint2 v0 = *(const uint2*)(p + (size_t)s0 * F + lane * 4);
        uint2 v1 = *(const uint2*)(p + (size_t)s1 * F + lane * 4);
        uint2 v2 = *(const uint2*)(p + (size_t)s2 * F + lane * 4);
        uint2 v3 = *(const uint2*)(p + (size_t)s3 * F + lane * 4);
        float2 a, b;
        a = __half22float2(*(__half2*)&v0.x); b = __half22float2(*(__half2*)&v0.y);
        acc.x += a.x; acc.y += a.y; acc.z += b.x; acc.w += b.y;
        a = __half22float2(*(__half2*)&v1.x); b = __half22float2(*(__half2*)&v1.y);
        acc.x += a.x; acc.y += a.y; acc.z += b.x; acc.w += b.y;
        a = __half22float2(*(__half2*)&v2.x); b = __half22float2(*(__half2*)&v2.y);
        acc.x += a.x; acc.y += a.y; acc.z += b.x; acc.w += b.y;
        a = __half22float2(*(__half2*)&v3.x); b = __half22float2(*(__half2*)&v3.y);
        acc.x += a.x; acc.y += a.y; acc.z += b.x; acc.w += b.y;
    }
    for (; i < r1; i++) {
        int s = g_csrc[i];
        uint2 v = *(const uint2*)(p + (size_t)s * F + lane * 4);
        float2 a = __half22float2(*(__half2*)&v.x);
        float2 b = __half22float2(*(__half2*)&v.y);
        acc.x += a.x; acc.y += a.y; acc.z += b.x; acc.w += b.y;
    }
    float inv = 1.0f / (float)max(r1 - r0, 1);
    __half2 m01 = __floats2half2_rn(acc.x * inv, acc.y * inv);
    __half2 m23 = __floats2half2_rn(acc.z * inv, acc.w * inv);
    uint2 pk;
    pk.x = *(unsigned*)&m01;
    pk.y = *(unsigned*)&m23;
    *(uint2*)(g_m16 + (size_t)gw * F + lane * 4) = pk;
}

// ---------------- HMMA fp16 GEMM (A exact fp16, W split fp16 hi/lo) ---------------
// MODE 0: h1 = relu(mean@W1 + x@W1r + b)  -> g_h1h16 fp16, K=256
// MODE 1: h2 = mean@W2 + h1@W2r + b       -> g_h2h16 fp16, K=256
// MODE 2: ABh[:, by*128..] = h2 @ wtc_by  -> g_ABh fp16, K=128, grid.y=2
#define SAPAD 40

template <int MODE>
__global__ __launch_bounds__(512)
void mma_gemm(const float* __restrict__ bias, int M)
{
    constexpr int NCHUNK = (MODE <= 1) ? 8 : 4;   // K-chunks of 32
    constexpr int KTOT   = (MODE <= 1) ? 256 : 128;
    const int wtoff = (MODE == 0) ? 0 : (MODE == 1) ? 32768
                     : 65536 + (int)blockIdx.y * 16384;

    __shared__ __half sA[128][SAPAD];
    __shared__ __half sWh[128][SAPAD], sWl[128][SAPAD];

    int tid  = threadIdx.x;
    int wid  = tid >> 5, lane = tid & 31;
    int m0   = blockIdx.x * 128;
    int wm   = wid >> 2, wn = wid & 3;
    int mb   = wm * 32,  nb = wn * 32;

    float acc[2][4][4];
#pragma unroll
    for (int mi = 0; mi < 2; mi++)
#pragma unroll
        for (int ni = 0; ni < 4; ni++)
#pragma unroll
            for (int q = 0; q < 4; q++) acc[mi][ni][q] = 0.f;

    const int frow = tid >> 2;            // 0..127
    const int fseg = (tid & 3) * 8;       // 0,8,16,24 (elems)
    const int gmf  = m0 + frow;

    const int a_r = (lane & 15);
    const int a_c = (lane >> 4) * 8;
    const int b_r = (lane & 7);
    const int b_c = ((lane >> 3) & 1) * 8;

    for (int ch = 0; ch < NCHUNK; ch++) {
        const __half* a16;
        int kk0;
        if (MODE == 2)      { a16 = g_h2h16; kk0 = ch * 32; }
        else if (ch < 4)    { a16 = g_m16;   kk0 = ch * 32; }
        else if (MODE == 0) { a16 = g_x16;   kk0 = (ch - 4) * 32; }
        else                { a16 = g_h1h16; kk0 = (ch - 4) * 32; }
        int kkw = ch * 32;

        {
            uint4 va = make_uint4(0, 0, 0, 0);
            if (gmf < M) va = *(const uint4*)(a16 + (size_t)gmf * F + kk0 + fseg);
            *(uint4*)&sA[frow][fseg] = va;
            *(uint4*)&sWh[frow][fseg] =
                *(const uint4*)(g_wt_hi + wtoff + (size_t)frow * KTOT + kkw + fseg);
            *(uint4*)&sWl[frow][fseg] =
                *(const uint4*)(g_wt_lo + wtoff + (size_t)frow * KTOT + kkw + fseg);
        }
        __syncthreads();

#pragma unroll
        for (int ks = 0; ks < 2; ks++) {
            uint32_t af[2][4], whf[4][2], wlf[4][2];
#pragma unroll
            for (int mi = 0; mi < 2; mi++)
                ldm_x4(af[mi], sm32(&sA[mb + mi * 16 + a_r][ks * 16 + a_c]));
#pragma unroll
            for (int ni = 0; ni < 4; ni++) {
                ldm_x2(whf[ni], sm32(&sWh[nb + ni * 8 + b_r][ks * 16 + b_c]));
                ldm_x2(wlf[ni], sm32(&sWl[nb + ni * 8 + b_r][ks * 16 + b_c]));
            }
#pragma unroll
            for (int mi = 0; mi < 2; mi++)
#pragma unroll
                for (int ni = 0; ni < 4; ni++) {
                    mma16816h(acc[mi][ni], af[mi], whf[ni]);
                    mma16816h(acc[mi][ni], af[mi], wlf[ni]);
                }
        }
        __syncthreads();
    }

    const int trow = lane >> 2;
    const int tcol = (lane & 3) * 2;
#pragma unroll
    for (int mi = 0; mi < 2; mi++) {
#pragma unroll
        for (int half = 0; half < 2; half++) {
            int m = m0 + mb + mi * 16 + trow + half * 8;
            if (m >= M) continue;
#pragma unroll
            for (int ni = 0; ni < 4; ni++) {
                int col = nb + ni * 8 + tcol;
                float vx = acc[mi][ni][half * 2 + 0];
                float vy = acc[mi][ni][half * 2 + 1];
                if (MODE <= 1) { vx += bias[col]; vy += bias[col + 1]; }
                if (MODE == 0) { vx = fmaxf(vx, 0.f); vy = fmaxf(vy, 0.f); }
                __half2 h = __floats2half2_rn(vx, vy);
                if (MODE == 0) {
                    *(__half2*)(g_h1h16 + (size_t)m * F + col) = h;
                } else if (MODE == 1) {
                    *(__half2*)(g_h2h16 + (size_t)m * F + col) = h;
                } else {
                    *(__half2*)(g_ABh + (size_t)m * 256 + blockIdx.y * 128 + col) = h;
                }
            }
        }
    }
}

// ---------------- edge classifier: warp per edge (fp16 AB table) -----------------
__global__ __launch_bounds__(256)
void edge_kernel(const void* __restrict__ eidx,
                 const float* __restrict__ ea,
                 const float* __restrict__ Wc1,
                 const float* __restrict__ bc1,
                 const float* __restrict__ Wc2,
                 const float* __restrict__ bc2,
                 float* __restrict__ out)
{
    __shared__ float sWe0[128], sWe1[128], sWe2[128], sb[128], sw2[128];
    int tid = threadIdx.x;
    if (tid < 128) {
        sWe0[tid] = Wc1[256 * 128 + tid];
        sWe1[tid] = Wc1[257 * 128 + tid];
        sWe2[tid] = Wc1[258 * 128 + tid];
        sb[tid]   = bc1[tid];
        sw2[tid]  = Wc2[tid];
    }
    __syncthreads();

    int e = blockIdx.x * (blockDim.x >> 5) + (tid >> 5);
    if (e >= NE) return;
    int lane = tid & 31;
    int j = lane * 4;

    int s = load_idx(eidx, e);
    int d = load_idx(eidx, (long long)NE + e);

    uint2 av = *(const uint2*)(g_ABh + (size_t)s * 256 + j);
    uint2 bv = *(const uint2*)(g_ABh + (size_t)d * 256 + 128 + j);
    float2 a01 = __half22float2(*(__half2*)&av.x);
    float2 a23 = __half22float2(*(__half2*)&av.y);
    float2 b01 = __half22float2(*(__half2*)&bv.x);
    float2 b23 = __half22float2(*(__half2*)&bv.y);

    float4 w0 = *(const float4*)&sWe0[j];
    float4 w1 = *(const float4*)&sWe1[j];
    float4 w2 = *(const float4*)&sWe2[j];
    float4 bb = *(const float4*)&sb[j];
    float4 wc = *(const float4*)&sw2[j];

    float e0 = ea[(size_t)e * 3 + 0];
    float e1 = ea[(size_t)e * 3 + 1];
    float e2 = ea[(size_t)e * 3 + 2];

    float h, acc = 0.f;
    h = a01.x + b01.x + e0 * w0.x + e1 * w1.x + e2 * w2.x + bb.x;
    acc += fmaxf(h, 0.f) * wc.x;
    h = a01.y + b01.y + e0 * w0.y + e1 * w1.y + e2 * w2.y + bb.y;
    acc += fmaxf(h, 0.f) * wc.y;
    h = a23.x + b23.x + e0 * w0.z + e1 * w1.z + e2 * w2.z + bb.z;
    acc += fmaxf(h, 0.f) * wc.z;
    h = a23.y + b23.y + e0 * w0.w + e1 * w1.w + e2 * w2.w + bb.w;
    acc += fmaxf(h, 0.f) * wc.w;

#pragma unroll
    for (int off = 16; off > 0; off >>= 1)
        acc += __shfl_xor_sync(0xFFFFFFFFu, acc, off);

    if (lane == 0) out[e] = acc + bc2[0];
}

// ---------------- launch -----------------------------------------------------------
extern "C" void kernel_launch(void* const* d_in, const int* in_sizes, int n_in,
                              void* d_out, int out_size)
{
    const float* x    = (const float*)d_in[0];
    const void*  eidx = d_in[1];
    const float* ea   = (const float*)d_in[2];
    const float* W1l  = (const float*)d_in[3];
    const float* b1l  = (const float*)d_in[4];
    const float* W1r  = (const float*)d_in[5];
    const float* W2l  = (const float*)d_in[6];
    const float* b2l  = (const float*)d_in[7];
    const float* W2r  = (const float*)d_in[8];
    const float* Wc1  = (const float*)d_in[9];
    const float* bc1  = (const float*)d_in[10];
    const float* Wc2  = (const float*)d_in[11];
    const float* bc2  = (const float*)d_in[12];
    float* out = (float*)d_out;

    const int SCAN_BLOCKS = (NN + 1023) / 1024;  // 49

    long long setup_threads = (long long)NN + 98304 + (long long)NN * 32;
    int setup_grid = (int)((setup_threads + 255) / 256);
    setup_kernel<<<setup_grid, 256>>>(eidx, x, W1l, W1r, W2l, W2r, Wc1);

    hist_kernel<<<(NE + 255) / 256, 256>>>(eidx);
    scanA_kernel<<<SCAN_BLOCKS, 1024>>>();
    scanB_kernel<<<1, 64>>>(SCAN_BLOCKS);
    scatter_kernel<<<(NE + 255) / 256, 256>>>(eidx);

    const int aggGrid  = (NN * 32 + 255) / 256;
    const int gemmGrid = (NN + 127) / 128;       // 391

    aggregate_kernel<0><<<aggGrid, 256>>>();
    mma_gemm<0><<<gemmGrid, 512>>>(b1l, NN);

    aggregate_kernel<1><<<aggGrid, 256>>>();
    mma_gemm<1><<<gemmGrid, 512>>>(b2l, NN);

    mma_gemm<2><<<dim3(gemmGrid, 2), 512>>>(nullptr, NN);

    edge_kernel<<<(NE * 32 + 255) / 256, 256>>>(eidx, ea, Wc1, bc1, Wc2, bc2, out);
}